// round 1
// baseline (speedup 1.0000x reference)
#include <cuda_runtime.h>
#include <stdint.h>

#define EPSF 1e-8f

constexpr int B = 8, N = 2048, D = 384, R = 64;
constexpr int HW = 256 * 256;
constexpr int W64 = N / 32;  // 64 bitmask words per adjacency row

// Output layout (float32, concatenated in reference return order)
constexpr size_t OUT_OFF  = 0;                      // (B,N,D)
constexpr size_t SEG_OFF  = (size_t)B * N * D;      // 6291456, (B,256,256)
constexpr size_t LOSS_OFF = SEG_OFF + (size_t)B * HW; // 6815744, scalar
constexpr size_t C_OFF    = LOSS_OFF + 1;           // 6815745, (B,N,R)

// ---------------- device scratch (static; no allocations) ----------------
__device__ uint32_t g_adj[(size_t)B * N * W64];   // 4 MB bitmask adjacency
__device__ float    g_S  [(size_t)B * N * R];     // 4 MB soft assignments
__device__ float    g_C  [(size_t)B * N * R];     // 4 MB softmax (aligned copy)
__device__ float4   g_kn4[(D / 4) * R];           // normalized prototypes, [k4][r] layout
__device__ float    g_mask[B * N];
__device__ float    g_f  [B * R];                 // column sums of S per batch
__device__ float    g_kl [B * N];                 // per-node kl*mask
__device__ int      g_is64;

// ---------------- helpers ----------------
__device__ __forceinline__ float warpSum(float v) {
    #pragma unroll
    for (int o = 16; o; o >>= 1) v += __shfl_xor_sync(0xffffffffu, v, o);
    return v;
}
__device__ __forceinline__ float warpMax(float v) {
    #pragma unroll
    for (int o = 16; o; o >>= 1) v = fmaxf(v, __shfl_xor_sync(0xffffffffu, v, o));
    return v;
}
__device__ __forceinline__ int seg_at(const void* seg, int idx, int is64) {
    if (is64) return (int)((const long long*)seg)[idx];
    return ((const int*)seg)[idx];
}

// ---------------- K_detect: int32 vs int64 segments ----------------
__global__ void k_detect(const unsigned int* __restrict__ seg) {
    if (blockIdx.x == 0 && threadIdx.x == 0) {
        unsigned int acc = 0;
        for (int i = 0; i < 128; i++) acc |= seg[2 * i + 1];
        // int64 little-endian with values < 2048 -> all high words are 0.
        g_is64 = (acc == 0u) ? 1 : 0;
    }
}

// ---------------- K0: init bitmask (diag=1), zero mask/f ----------------
__global__ void k_init() {
    int idx = blockIdx.x * blockDim.x + threadIdx.x;  // covers B*N*W64 = 1048576
    int row = idx >> 6;       // b*N+n
    int w   = idx & 63;
    int n   = row & (N - 1);
    g_adj[idx] = (w == (n >> 5)) ? (1u << (n & 31)) : 0u;
    if (idx < B * N) g_mask[idx] = 0.0f;
    if (idx < B * R) g_f[idx] = 0.0f;
}

// ---------------- K1: adjacency bits + presence mask ----------------
__global__ void k_adj(const void* __restrict__ seg) {
    int idx = blockIdx.x * blockDim.x + threadIdx.x;
    if (idx >= B * HW) return;
    int is64 = g_is64;
    int b = idx >> 16;
    int p = idx & 65535;
    int yy = p >> 8, xx = p & 255;
    int s = seg_at(seg, idx, is64);
    g_mask[b * N + s] = 1.0f;
    if (xx < 255) {
        int t = seg_at(seg, idx + 1, is64);
        if (s != t && s != 0 && t != 0) {
            atomicOr(&g_adj[((size_t)(b * N + s) << 6) + (t >> 5)], 1u << (t & 31));
            atomicOr(&g_adj[((size_t)(b * N + t) << 6) + (s >> 5)], 1u << (s & 31));
        }
    }
    if (yy < 255) {
        int t = seg_at(seg, idx + 256, is64);
        if (s != t && s != 0 && t != 0) {
            atomicOr(&g_adj[((size_t)(b * N + s) << 6) + (t >> 5)], 1u << (t & 31));
            atomicOr(&g_adj[((size_t)(b * N + t) << 6) + (s >> 5)], 1u << (s & 31));
        }
    }
}

// ---------------- K2: normalized prototypes, layout [k/4][r] as float4 ----------------
__global__ void k_kn(const float* __restrict__ protos) {
    int r = blockIdx.x;          // 64 blocks
    int tid = threadIdx.x;       // 128 threads
    __shared__ float red[4];
    float ss = 0.f;
    for (int k = tid; k < D; k += 128) {
        float v = protos[r * D + k];
        ss += v * v;
    }
    ss = warpSum(ss);
    if ((tid & 31) == 0) red[tid >> 5] = ss;
    __syncthreads();
    float tot = red[0] + red[1] + red[2] + red[3];
    float inv = 1.0f / fmaxf(sqrtf(tot), EPSF);
    for (int k4 = tid; k4 < D / 4; k4 += 128) {
        float4 v;
        v.x = protos[r * D + 4 * k4 + 0] * inv;
        v.y = protos[r * D + 4 * k4 + 1] * inv;
        v.z = protos[r * D + 4 * k4 + 2] * inv;
        v.w = protos[r * D + 4 * k4 + 3] * inv;
        g_kn4[k4 * R + r] = v;
    }
}

// ---------------- K3: S = row-normalized (cos+1)/2 ----------------
__global__ void __launch_bounds__(64) k_S(const float* __restrict__ x) {
    int row = blockIdx.x;        // b*N+n
    int tid = threadIdx.x;       // 0..63 (= r)
    __shared__ float4 xs[D / 4];
    __shared__ float red[2], red2[2];
    float ss = 0.f;
    const float4* xr = (const float4*)(x + (size_t)row * D);
    for (int k4 = tid; k4 < D / 4; k4 += 64) {
        float4 v = xr[k4];
        xs[k4] = v;
        ss += v.x * v.x + v.y * v.y + v.z * v.z + v.w * v.w;
    }
    ss = warpSum(ss);
    if ((tid & 31) == 0) red[tid >> 5] = ss;
    __syncthreads();
    float inv = 1.0f / fmaxf(sqrtf(red[0] + red[1]), EPSF);
    float dot = 0.f;
    #pragma unroll 4
    for (int k4 = 0; k4 < D / 4; k4++) {
        float4 v = xs[k4];
        float4 w = g_kn4[k4 * R + tid];
        dot += v.x * w.x + v.y * w.y + v.z * w.z + v.w * w.w;
    }
    float csim = (dot * inv + 1.0f) * 0.5f;
    float s = warpSum(csim);
    if ((tid & 31) == 0) red2[tid >> 5] = s;
    __syncthreads();
    float tot = red2[0] + red2[1];
    g_S[(size_t)row * R + tid] = csim / tot;
}

// ---------------- K4: f[b][r] = sum_n S (deterministic tree) ----------------
__global__ void k_f() {
    int br = blockIdx.x;         // b*R + r, 512 blocks
    int b = br >> 6, r = br & 63;
    int tid = threadIdx.x;       // 256
    float acc = 0.f;
    for (int n = tid; n < N; n += 256)
        acc += g_S[((size_t)(b * N + n)) * R + r];
    acc = warpSum(acc);
    __shared__ float red[8];
    if ((tid & 31) == 0) red[tid >> 5] = acc;
    __syncthreads();
    if (tid == 0) {
        float t = 0.f;
        #pragma unroll
        for (int i = 0; i < 8; i++) t += red[i];
        g_f[br] = t;
    }
}

// ---------------- K5: C = softmax(S), per-node KL ----------------
__global__ void k_C(float* __restrict__ outC) {
    int gw = (blockIdx.x * blockDim.x + threadIdx.x) >> 5;
    if (gw >= B * N) return;
    int lane = threadIdx.x & 31;
    int row = gw, b = row >> 11;
    const float* Sr = &g_S[(size_t)row * R];
    float s0 = Sr[lane], s1 = Sr[lane + 32];
    float f0 = g_f[b * R + lane], f1 = g_f[b * R + lane + 32];
    float p0 = s0 * s0 / (f0 + EPSF), p1 = s1 * s1 / (f1 + EPSF);
    float ps = warpSum(p0 + p1);
    p0 /= (ps + EPSF); p1 /= (ps + EPSF);
    float kl = p0 * (logf(p0 + EPSF) - logf(s0 + EPSF))
             + p1 * (logf(p1 + EPSF) - logf(s1 + EPSF));
    kl = warpSum(kl);
    float mx = warpMax(fmaxf(s0, s1));
    float e0 = expf(s0 - mx), e1 = expf(s1 - mx);
    float es = warpSum(e0 + e1);
    float c0 = e0 / es, c1 = e1 / es;
    g_C[(size_t)row * R + lane] = c0;
    g_C[(size_t)row * R + lane + 32] = c1;
    outC[(size_t)row * R + lane] = c0;
    outC[(size_t)row * R + lane + 32] = c1;
    if (lane == 0) g_kl[row] = kl * g_mask[row];
}

// ---------------- K6: loss scalar (deterministic) ----------------
__global__ void k_loss(float* __restrict__ outLoss) {
    int tid = threadIdx.x;   // 256, 1 block
    float a = 0.f, mm = 0.f;
    for (int i = tid; i < B * N; i += 256) { a += g_kl[i]; mm += g_mask[i]; }
    a = warpSum(a); mm = warpSum(mm);
    __shared__ float ra[8], rm[8];
    if ((tid & 31) == 0) { ra[tid >> 5] = a; rm[tid >> 5] = mm; }
    __syncthreads();
    if (tid == 0) {
        float A = 0.f, M = 0.f;
        #pragma unroll
        for (int i = 0; i < 8; i++) { A += ra[i]; M += rm[i]; }
        *outLoss = A / (M + EPSF);
    }
}

// ---------------- K7: segments passthrough (cast to float) ----------------
__global__ void k_seg(const void* __restrict__ seg, float* __restrict__ outSeg) {
    int i = blockIdx.x * blockDim.x + threadIdx.x;
    if (i < B * HW) outSeg[i] = (float)seg_at(seg, i, g_is64);
}

// ---------------- K8: masked affinity pooling (dominant) ----------------
__global__ void __launch_bounds__(256) k_pool(const float* __restrict__ x,
                                              float* __restrict__ out) {
    int row = blockIdx.x;            // b*N+n
    int b = row >> 11;
    int tid = threadIdx.x, warp = tid >> 5, lane = tid & 31;
    __shared__ float4 psum4[8 * 96]; // per-warp partial out rows (8 x 384 floats)
    __shared__ float  pws[8];

    // C_n pair for this lane (2*lane, 2*lane+1), and ||C_n||
    const float2* Crow = (const float2*)&g_C[(size_t)row * R];
    float2 cn2 = Crow[lane];
    float cn_n = sqrtf(warpSum(cn2.x * cn2.x + cn2.y * cn2.y));

    float4 a0 = make_float4(0.f, 0.f, 0.f, 0.f), a1 = a0, a2 = a0;
    float wsum = 0.f;
    const uint32_t* adjrow = &g_adj[(size_t)row << 6];
    const float* xb = x + (size_t)b * N * D;

    for (int wi = warp; wi < W64; wi += 8) {
        uint32_t bits = adjrow[wi];
        while (bits) {
            int bitp = __ffs(bits) - 1;
            bits &= bits - 1;
            int m = (wi << 5) + bitp;
            const float2* Cm = (const float2*)&g_C[(size_t)(b * N + m) * R];
            float2 cm2 = Cm[lane];
            float dotp = cm2.x * cn2.x + cm2.y * cn2.y;
            float ssp  = cm2.x * cm2.x + cm2.y * cm2.y;
            #pragma unroll
            for (int o = 16; o; o >>= 1) {
                dotp += __shfl_xor_sync(0xffffffffu, dotp, o);
                ssp  += __shfl_xor_sync(0xffffffffu, ssp,  o);
            }
            float w = dotp / (cn_n * sqrtf(ssp) + EPSF);
            wsum += w;
            const float4* xr = (const float4*)(xb + (size_t)m * D);
            float4 v0 = xr[lane], v1 = xr[lane + 32], v2 = xr[lane + 64];
            a0.x += w * v0.x; a0.y += w * v0.y; a0.z += w * v0.z; a0.w += w * v0.w;
            a1.x += w * v1.x; a1.y += w * v1.y; a1.z += w * v1.z; a1.w += w * v1.w;
            a2.x += w * v2.x; a2.y += w * v2.y; a2.z += w * v2.z; a2.w += w * v2.w;
        }
    }
    float4* ps = &psum4[warp * 96];
    ps[lane] = a0; ps[lane + 32] = a1; ps[lane + 64] = a2;
    if (lane == 0) pws[warp] = wsum;
    __syncthreads();
    float wst = 0.f;
    #pragma unroll
    for (int i = 0; i < 8; i++) wst += pws[i];
    float inv = 1.0f / (wst + EPSF);
    const float* psf = (const float*)psum4;
    for (int d = tid; d < D; d += 256) {
        float t = 0.f;
        #pragma unroll
        for (int w2 = 0; w2 < 8; w2++) t += psf[w2 * 384 + d];
        out[(size_t)row * D + d] = t * inv;
    }
}

// ---------------- launch ----------------
extern "C" void kernel_launch(void* const* d_in, const int* in_sizes, int n_in,
                              void* d_out, int out_size) {
    const float* x      = (const float*)d_in[0];
    const void*  seg    = d_in[1];
    const float* protos = (const float*)d_in[2];
    float* out = (float*)d_out;

    float* outSeg  = out + SEG_OFF;
    float* outLoss = out + LOSS_OFF;
    float* outC    = out + C_OFF;

    k_detect<<<1, 32>>>((const unsigned int*)seg);
    k_init<<<(B * N * W64) / 256, 256>>>();
    k_adj<<<(B * HW) / 256, 256>>>(seg);
    k_kn<<<R, 128>>>(protos);
    k_S<<<B * N, 64>>>(x);
    k_f<<<B * R, 256>>>();
    k_C<<<(B * N) / 4, 128>>>(outC);
    k_loss<<<1, 256>>>(outLoss);
    k_seg<<<(B * HW) / 256, 256>>>(seg, outSeg);
    k_pool<<<B * N, 256>>>(x, out);
}

// round 3
// speedup vs baseline: 1.2053x; 1.2053x over previous
#include <cuda_runtime.h>
#include <cuda_fp16.h>
#include <stdint.h>

#define EPSF 1e-8f

constexpr int B = 8, N = 2048, D = 384, R = 64;
constexpr int HW = 256 * 256;
constexpr int W64 = N / 32;  // 64 bitmask words per adjacency row

// Output layout (float32, concatenated in reference return order)
constexpr size_t OUT_OFF  = 0;                        // (B,N,D)
constexpr size_t SEG_OFF  = (size_t)B * N * D;        // 6291456, (B,256,256)
constexpr size_t LOSS_OFF = SEG_OFF + (size_t)B * HW; // 6815744, scalar
constexpr size_t C_OFF    = LOSS_OFF + 1;             // 6815745, (B,N,R)

// ---------------- device scratch (static; no allocations) ----------------
__device__ uint32_t g_adj[(size_t)B * N * W64];  // 4 MB bitmask adjacency
__device__ float    g_S  [(size_t)B * N * R];    // 4 MB soft assignments
__device__ __half   g_Ch [(size_t)B * N * R];    // 2 MB normalized Chat (fp16)
__device__ __half   g_xh [(size_t)B * N * D];    // 12 MB x in fp16
__device__ float4   g_kn4[(D / 4) * R];          // normalized prototypes, [k4][r]
__device__ float    g_mask[B * N];
__device__ float    g_f  [B * R];                // column sums of S per batch
__device__ float    g_kl [B * N];                // per-node kl*mask
__device__ int      g_is64;

// ---------------- helpers ----------------
__device__ __forceinline__ float warpSum(float v) {
    #pragma unroll
    for (int o = 16; o; o >>= 1) v += __shfl_xor_sync(0xffffffffu, v, o);
    return v;
}
__device__ __forceinline__ float warpMax(float v) {
    #pragma unroll
    for (int o = 16; o; o >>= 1) v = fmaxf(v, __shfl_xor_sync(0xffffffffu, v, o));
    return v;
}
__device__ __forceinline__ int seg_at(const void* seg, int idx, int is64) {
    if (is64) return (int)((const long long*)seg)[idx];
    return ((const int*)seg)[idx];
}

// ---------------- K_detect: int32 vs int64 segments ----------------
__global__ void k_detect(const unsigned int* __restrict__ seg) {
    if (blockIdx.x == 0 && threadIdx.x == 0) {
        unsigned int acc = 0;
        for (int i = 0; i < 128; i++) acc |= seg[2 * i + 1];
        g_is64 = (acc == 0u) ? 1 : 0;  // int64 LE, values<2048 -> high words 0
    }
}

// ---------------- K0: init bitmask (diag=1), zero mask/f ----------------
__global__ void k_init() {
    int idx = blockIdx.x * blockDim.x + threadIdx.x;  // covers B*N*W64 = 1048576
    int row = idx >> 6;
    int w   = idx & 63;
    int n   = row & (N - 1);
    g_adj[idx] = (w == (n >> 5)) ? (1u << (n & 31)) : 0u;
    if (idx < B * N) g_mask[idx] = 0.0f;
    if (idx < B * R) g_f[idx] = 0.0f;
}

// ---------------- K1: adjacency bits + presence mask ----------------
__global__ void k_adj(const void* __restrict__ seg) {
    int idx = blockIdx.x * blockDim.x + threadIdx.x;
    if (idx >= B * HW) return;
    int is64 = g_is64;
    int b = idx >> 16;
    int p = idx & 65535;
    int yy = p >> 8, xx = p & 255;
    int s = seg_at(seg, idx, is64);
    g_mask[b * N + s] = 1.0f;
    if (xx < 255) {
        int t = seg_at(seg, idx + 1, is64);
        if (s != t && s != 0 && t != 0) {
            atomicOr(&g_adj[((size_t)(b * N + s) << 6) + (t >> 5)], 1u << (t & 31));
            atomicOr(&g_adj[((size_t)(b * N + t) << 6) + (s >> 5)], 1u << (s & 31));
        }
    }
    if (yy < 255) {
        int t = seg_at(seg, idx + 256, is64);
        if (s != t && s != 0 && t != 0) {
            atomicOr(&g_adj[((size_t)(b * N + s) << 6) + (t >> 5)], 1u << (t & 31));
            atomicOr(&g_adj[((size_t)(b * N + t) << 6) + (s >> 5)], 1u << (s & 31));
        }
    }
}

// ---------------- K2: normalized prototypes, [k/4][r] float4 layout ----------------
__global__ void k_kn(const float* __restrict__ protos) {
    int r = blockIdx.x;          // 64 blocks
    int tid = threadIdx.x;       // 128 threads
    __shared__ float red[4];
    float ss = 0.f;
    for (int k = tid; k < D; k += 128) {
        float v = protos[r * D + k];
        ss += v * v;
    }
    ss = warpSum(ss);
    if ((tid & 31) == 0) red[tid >> 5] = ss;
    __syncthreads();
    float tot = red[0] + red[1] + red[2] + red[3];
    float inv = 1.0f / fmaxf(sqrtf(tot), EPSF);
    for (int k4 = tid; k4 < D / 4; k4 += 128) {
        float4 v;
        v.x = protos[r * D + 4 * k4 + 0] * inv;
        v.y = protos[r * D + 4 * k4 + 1] * inv;
        v.z = protos[r * D + 4 * k4 + 2] * inv;
        v.w = protos[r * D + 4 * k4 + 3] * inv;
        g_kn4[k4 * R + r] = v;
    }
}

// ---------------- K_xh: x -> fp16 shadow copy ----------------
__global__ void k_xh(const float* __restrict__ x) {
    int i = blockIdx.x * blockDim.x + threadIdx.x;   // B*N*D/2 float2s
    if (i >= (B * N * D) / 2) return;
    float2 v = ((const float2*)x)[i];
    ((__half2*)g_xh)[i] = __float22half2_rn(v);
}

// ---------------- K3: S = row-normalized (cos+1)/2 ----------------
__global__ void __launch_bounds__(64) k_S(const float* __restrict__ x) {
    int row = blockIdx.x;        // b*N+n
    int tid = threadIdx.x;       // 0..63 (= r)
    __shared__ float4 xs[D / 4];
    __shared__ float red[2], red2[2];
    float ss = 0.f;
    const float4* xr = (const float4*)(x + (size_t)row * D);
    for (int k4 = tid; k4 < D / 4; k4 += 64) {
        float4 v = xr[k4];
        xs[k4] = v;
        ss += v.x * v.x + v.y * v.y + v.z * v.z + v.w * v.w;
    }
    ss = warpSum(ss);
    if ((tid & 31) == 0) red[tid >> 5] = ss;
    __syncthreads();
    float inv = 1.0f / fmaxf(sqrtf(red[0] + red[1]), EPSF);
    float dot = 0.f;
    #pragma unroll 4
    for (int k4 = 0; k4 < D / 4; k4++) {
        float4 v = xs[k4];
        float4 w = g_kn4[k4 * R + tid];
        dot += v.x * w.x + v.y * w.y + v.z * w.z + v.w * w.w;
    }
    float csim = (dot * inv + 1.0f) * 0.5f;
    float s = warpSum(csim);
    if ((tid & 31) == 0) red2[tid >> 5] = s;
    __syncthreads();
    float tot = red2[0] + red2[1];
    g_S[(size_t)row * R + tid] = csim / tot;
}

// ---------------- K4: f[b][r] = sum_n S (deterministic tree) ----------------
__global__ void k_f() {
    int br = blockIdx.x;         // b*R + r, 512 blocks
    int b = br >> 6, r = br & 63;
    int tid = threadIdx.x;       // 256
    float acc = 0.f;
    for (int n = tid; n < N; n += 256)
        acc += g_S[((size_t)(b * N + n)) * R + r];
    acc = warpSum(acc);
    __shared__ float red[8];
    if ((tid & 31) == 0) red[tid >> 5] = acc;
    __syncthreads();
    if (tid == 0) {
        float t = 0.f;
        #pragma unroll
        for (int i = 0; i < 8; i++) t += red[i];
        g_f[br] = t;
    }
}

// ---------------- K5: C = softmax(S), Chat fp16, per-node KL ----------------
__global__ void k_C(float* __restrict__ outC) {
    int gw = (blockIdx.x * blockDim.x + threadIdx.x) >> 5;
    if (gw >= B * N) return;
    int lane = threadIdx.x & 31;
    int row = gw, b = row >> 11;
    const float* Sr = &g_S[(size_t)row * R];
    float s0 = Sr[lane], s1 = Sr[lane + 32];
    float f0 = g_f[b * R + lane], f1 = g_f[b * R + lane + 32];
    float p0 = s0 * s0 / (f0 + EPSF), p1 = s1 * s1 / (f1 + EPSF);
    float ps = warpSum(p0 + p1);
    p0 /= (ps + EPSF); p1 /= (ps + EPSF);
    float kl = p0 * (logf(p0 + EPSF) - logf(s0 + EPSF))
             + p1 * (logf(p1 + EPSF) - logf(s1 + EPSF));
    kl = warpSum(kl);
    float mx = warpMax(fmaxf(s0, s1));
    float e0 = expf(s0 - mx), e1 = expf(s1 - mx);
    float es = warpSum(e0 + e1);
    float c0 = e0 / es, c1 = e1 / es;
    outC[(size_t)row * R + lane] = c0;
    outC[(size_t)row * R + lane + 32] = c1;
    // pre-normalized Chat in fp16 for the pooling gather
    float nrm = warpSum(c0 * c0 + c1 * c1);
    float invn = rsqrtf(nrm);
    g_Ch[(size_t)row * R + lane]      = __float2half_rn(c0 * invn);
    g_Ch[(size_t)row * R + lane + 32] = __float2half_rn(c1 * invn);
    if (lane == 0) g_kl[row] = kl * g_mask[row];
}

// ---------------- K6: loss scalar (deterministic) ----------------
__global__ void k_loss(float* __restrict__ outLoss) {
    int tid = threadIdx.x;   // 256, 1 block
    float a = 0.f, mm = 0.f;
    for (int i = tid; i < B * N; i += 256) { a += g_kl[i]; mm += g_mask[i]; }
    a = warpSum(a); mm = warpSum(mm);
    __shared__ float ra[8], rm[8];
    if ((tid & 31) == 0) { ra[tid >> 5] = a; rm[tid >> 5] = mm; }
    __syncthreads();
    if (tid == 0) {
        float A = 0.f, M = 0.f;
        #pragma unroll
        for (int i = 0; i < 8; i++) { A += ra[i]; M += rm[i]; }
        *outLoss = A / (M + EPSF);
    }
}

// ---------------- K7: segments passthrough (cast to float) ----------------
__global__ void k_seg(const void* __restrict__ seg, float* __restrict__ outSeg) {
    int i = blockIdx.x * blockDim.x + threadIdx.x;
    if (i < B * HW) outSeg[i] = (float)seg_at(seg, i, g_is64);
}

// ---------------- K8: masked affinity pooling, fp16 gather ----------------
__global__ void __launch_bounds__(256) k_pool(float* __restrict__ out) {
    int row = blockIdx.x;            // b*N+n
    int b = row >> 11;
    int tid = threadIdx.x, warp = tid >> 5, lane = tid & 31;
    __shared__ float4 psum4[8 * 96]; // per-warp partial out rows (8 x 384 floats)
    __shared__ float  pws[8];

    // own normalized Chat: 2 components per lane
    const __half2* Crow = (const __half2*)&g_Ch[(size_t)row * R];
    float2 cn2 = __half22float2(Crow[lane]);

    float4 a0 = make_float4(0.f, 0.f, 0.f, 0.f), a1 = a0, a2 = a0;
    float wsum = 0.f;
    const uint32_t* adjrow = &g_adj[(size_t)row << 6];
    const __half* xh = g_xh + (size_t)b * N * D;

    for (int wi = warp; wi < W64; wi += 8) {
        uint32_t bits = adjrow[wi];
        while (bits) {
            int bitp = __ffs(bits) - 1;
            bits &= bits - 1;
            int m = (wi << 5) + bitp;

            // weight = Chat_n . Chat_m  (both pre-normalized)
            float2 cm2 = __half22float2(
                ((const __half2*)&g_Ch[(size_t)(b * N + m) * R])[lane]);
            float dotp = cm2.x * cn2.x + cm2.y * cn2.y;
            dotp = warpSum(dotp);
            wsum += dotp;

            // gather fp16 x row: 96 uint2 (4 halves each), lanes cover 3 each
            const uint2* xr = (const uint2*)(xh + (size_t)m * D);
            uint2 u0 = xr[lane], u1 = xr[lane + 32], u2 = xr[lane + 64];
            float2 f;
            f = __half22float2(*(const __half2*)&u0.x);
            a0.x += dotp * f.x; a0.y += dotp * f.y;
            f = __half22float2(*(const __half2*)&u0.y);
            a0.z += dotp * f.x; a0.w += dotp * f.y;
            f = __half22float2(*(const __half2*)&u1.x);
            a1.x += dotp * f.x; a1.y += dotp * f.y;
            f = __half22float2(*(const __half2*)&u1.y);
            a1.z += dotp * f.x; a1.w += dotp * f.y;
            f = __half22float2(*(const __half2*)&u2.x);
            a2.x += dotp * f.x; a2.y += dotp * f.y;
            f = __half22float2(*(const __half2*)&u2.y);
            a2.z += dotp * f.x; a2.w += dotp * f.y;
        }
    }
    float4* ps = &psum4[warp * 96];
    ps[lane] = a0; ps[lane + 32] = a1; ps[lane + 64] = a2;
    if (lane == 0) pws[warp] = wsum;
    __syncthreads();
    float wst = 0.f;
    #pragma unroll
    for (int i = 0; i < 8; i++) wst += pws[i];
    float inv = 1.0f / (wst + EPSF);
    const float* psf = (const float*)psum4;
    for (int d = tid; d < D; d += 256) {
        float t = 0.f;
        #pragma unroll
        for (int w2 = 0; w2 < 8; w2++) t += psf[w2 * 384 + d];
        out[(size_t)row * D + d] = t * inv;
    }
}

// ---------------- launch ----------------
extern "C" void kernel_launch(void* const* d_in, const int* in_sizes, int n_in,
                              void* d_out, int out_size) {
    const float* x      = (const float*)d_in[0];
    const void*  seg    = d_in[1];
    const float* protos = (const float*)d_in[2];
    float* out = (float*)d_out;

    float* outSeg  = out + SEG_OFF;
    float* outLoss = out + LOSS_OFF;
    float* outC    = out + C_OFF;

    k_detect<<<1, 32>>>((const unsigned int*)seg);
    k_init<<<(B * N * W64) / 256, 256>>>();
    k_adj<<<(B * HW) / 256, 256>>>(seg);
    k_kn<<<R, 128>>>(protos);
    k_xh<<<(B * N * D / 2 + 255) / 256, 256>>>(x);
    k_S<<<B * N, 64>>>(x);
    k_f<<<B * R, 256>>>();
    k_C<<<(B * N) / 4, 128>>>(outC);
    k_loss<<<1, 256>>>(outLoss);
    k_seg<<<(B * HW) / 256, 256>>>(seg, outSeg);
    k_pool<<<B * N, 256>>>(out);
}